// round 16
// baseline (speedup 1.0000x reference)
#include <cuda_runtime.h>
#include <cuda_bf16.h>
#include <cstdint>
#include <math.h>

#define NDIM 512
#define C 128
#define NN (NDIM*NDIM)
#define PLANE NN
#define WFB 67584          // 128 x 132 f32 array bytes
#define XFB 33792          // 64 x 132 f32 array bytes
#define WCH 18432          // 128 n x 36 f32 (144 B) weight k-chunk bytes

// ---------------------------------------------------------------------------
// scratch
// ---------------------------------------------------------------------------
__device__ __align__(16) float g_i[(size_t)C*NN];     // tf32-rounded, channel-major
__device__ __align__(16) float g_j[(size_t)C*NN];
__device__ __align__(16) float g_ecm[(size_t)C*NN];
__device__ __align__(16) float g_sg [(size_t)NN*C];
__device__ __align__(16) float g_wf[6 * 128 * 128];   // tf32 [n][k]: Wis Wi Wjs Wj Ws Wp

extern __shared__ char smem_[];

// ---------------------------------------------------------------------------
// PTX helpers
// ---------------------------------------------------------------------------
__device__ __forceinline__ uint32_t smem_u32(const void* p) {
    uint32_t a;
    asm("{ .reg .u64 t; cvta.to.shared.u64 t, %1; cvt.u32.u64 %0, t; }" : "=r"(a) : "l"(p));
    return a;
}
__device__ __forceinline__ void ldm_x4(uint32_t addr, uint32_t* r) {
    asm volatile("ldmatrix.sync.aligned.m8n8.x4.shared.b16 {%0,%1,%2,%3}, [%4];"
        : "=r"(r[0]), "=r"(r[1]), "=r"(r[2]), "=r"(r[3]) : "r"(addr));
}
__device__ __forceinline__ void mma_tf32(float* d, const uint32_t* a, uint32_t b0, uint32_t b1) {
    asm volatile("mma.sync.aligned.m16n8k8.row.col.f32.tf32.tf32.f32 "
        "{%0,%1,%2,%3}, {%4,%5,%6,%7}, {%8,%9}, {%0,%1,%2,%3};"
        : "+f"(d[0]), "+f"(d[1]), "+f"(d[2]), "+f"(d[3])
        : "r"(a[0]), "r"(a[1]), "r"(a[2]), "r"(a[3]), "r"(b0), "r"(b1));
}
__device__ __forceinline__ void cp16(uint32_t dst, const void* src) {
    asm volatile("cp.async.cg.shared.global [%0], [%1], 16;" :: "r"(dst), "l"(src) : "memory");
}
#define CP_COMMIT() asm volatile("cp.async.commit_group;" ::: "memory")
#define CP_WAIT(n)  asm volatile("cp.async.wait_group %0;" :: "n"(n) : "memory")
__device__ __forceinline__ float sigmoidf_(float x) { return 1.0f / (1.0f + __expf(-x)); }
__device__ __forceinline__ float tf32r(float x) {
    float r;
    asm("cvt.rna.tf32.f32 %0, %1;" : "=f"(r) : "f"(x));
    return r;
}

// ---------------------------------------------------------------------------
// Prologue: transpose + tf32-round weights
// ---------------------------------------------------------------------------
__global__ void convert_w_kernel(const float* __restrict__ Wis, const float* __restrict__ Wi,
                                 const float* __restrict__ Wjs, const float* __restrict__ Wj,
                                 const float* __restrict__ Ws,  const float* __restrict__ Wp) {
    const float* src[6] = {Wis, Wi, Wjs, Wj, Ws, Wp};
    const float* W = src[blockIdx.x];
    float* outp = g_wf + (size_t)blockIdx.x * 16384;
    for (int idx = threadIdx.x; idx < 16384; idx += blockDim.x) {
        int n = idx >> 7, k = idx & 127;
        outp[n * 128 + k] = tf32r(W[k * 128 + n]);
    }
}

// cp.async one tf32 weight [128 n][132 f32 stride] into smem, 256 threads
__device__ __forceinline__ void loadWf(int m, uint32_t sW, int tid) {
    const char* src = (const char*)g_wf + (size_t)m * 65536;
    #pragma unroll
    for (int it = 0; it < 16; ++it) {
        int idx = tid + it * 256;
        int row = idx >> 5, ch = idx & 31;
        cp16(sW + row * 528 + ch * 16, src + row * 512 + ch * 16);
    }
}

// cp.async one weight k-chunk (weight m, k-quarter q) into ring buf `buf`
__device__ __forceinline__ void loadWchunkTo(int m, int q, int buf, uint32_t sRing, int tid) {
    const char* src = (const char*)g_wf + (size_t)m * 65536 + q * 128;
    uint32_t dst = sRing + (uint32_t)buf * WCH;
    #pragma unroll
    for (int it = 0; it < 4; ++it) {
        int idx = tid + it * 256;
        int row = idx >> 3, ch = idx & 7;
        cp16(dst + row * 144 + ch * 16, src + (size_t)row * 512 + ch * 16);
    }
    CP_COMMIT();
}

// ---------------------------------------------------------------------------
// tf32 warp GEMM full-K (stage3): 32x32 warp tile, K=128, stride 528 B
// acc[(ma*4+na)*4+q]: q=0:(g,t2) 1:(g,t2+1) 2:(g+8,t2) 3:(g+8,t2+1)
// ---------------------------------------------------------------------------
__device__ __forceinline__ void wgemm_t32(uint32_t sA, uint32_t sB,
                                          int lane, int wm, int wn, float* acc) {
    int lr = lane & 7, sel = lane >> 3;
    uint32_t aRow = (uint32_t)((wm*32 + (sel & 1)*8 + lr) * 528 + (sel >> 1)*16);
    uint32_t bRow = (uint32_t)((wn*32 + (sel & 1)*8 + lr) * 528 + (sel >> 1)*16);
    #pragma unroll
    for (int kk = 0; kk < 16; ++kk) {
        uint32_t a[2][4];
        #pragma unroll
        for (int ma = 0; ma < 2; ++ma)
            ldm_x4(sA + aRow + (uint32_t)(ma * 16 * 528 + kk * 32), a[ma]);
        #pragma unroll
        for (int p = 0; p < 2; ++p) {
            uint32_t b[4];
            ldm_x4(sB + bRow + (uint32_t)(p * 16 * 528 + kk * 32), b);
            #pragma unroll
            for (int ma = 0; ma < 2; ++ma) {
                mma_tf32(acc + (ma*4 + p*2 + 0)*4, a[ma], b[0], b[2]);
                mma_tf32(acc + (ma*4 + p*2 + 1)*4, a[ma], b[1], b[3]);
            }
        }
    }
}

// single k-chunk GEMM: A [64 r][528 B] at k-offset aOff, B chunk [128 n][144 B]
__device__ __forceinline__ void wgemm_chunk(uint32_t sA, uint32_t aOff, uint32_t sB,
                                            int lane, int wm, int wn, float* acc) {
    int lr = lane & 7, sel = lane >> 3;
    uint32_t aRow = (uint32_t)((wm*32 + (sel & 1)*8 + lr) * 528 + (sel >> 1)*16) + aOff;
    uint32_t bRow = (uint32_t)((wn*32 + (sel & 1)*8 + lr) * 144 + (sel >> 1)*16);
    #pragma unroll
    for (int kk = 0; kk < 4; ++kk) {
        uint32_t a[2][4];
        #pragma unroll
        for (int ma = 0; ma < 2; ++ma)
            ldm_x4(sA + aRow + (uint32_t)(ma * 16 * 528 + kk * 32), a[ma]);
        #pragma unroll
        for (int p = 0; p < 2; ++p) {
            uint32_t b[4];
            ldm_x4(sB + bRow + (uint32_t)(p * 16 * 144 + kk * 32), b);
            #pragma unroll
            for (int ma = 0; ma < 2; ++ma) {
                mma_tf32(acc + (ma*4 + p*2 + 0)*4, a[ma], b[0], b[2]);
                mma_tf32(acc + (ma*4 + p*2 + 1)*4, a[ma], b[1], b[3]);
            }
        }
    }
}

// dual k-chunk GEMM: shared A fragments, gate B buf + main B buf
__device__ __forceinline__ void wgemm_chunk_dual(uint32_t sA, uint32_t aOff,
                                                 uint32_t sBg, uint32_t sBm,
                                                 int lane, int wm, int wn,
                                                 float* accg, float* accm) {
    int lr = lane & 7, sel = lane >> 3;
    uint32_t aRow = (uint32_t)((wm*32 + (sel & 1)*8 + lr) * 528 + (sel >> 1)*16) + aOff;
    uint32_t bRow = (uint32_t)((wn*32 + (sel & 1)*8 + lr) * 144 + (sel >> 1)*16);
    #pragma unroll
    for (int kk = 0; kk < 4; ++kk) {
        uint32_t a[2][4];
        #pragma unroll
        for (int ma = 0; ma < 2; ++ma)
            ldm_x4(sA + aRow + (uint32_t)(ma * 16 * 528 + kk * 32), a[ma]);
        #pragma unroll
        for (int p = 0; p < 2; ++p) {
            uint32_t off = bRow + (uint32_t)(p * 16 * 144 + kk * 32);
            uint32_t b[4];
            ldm_x4(sBg + off, b);
            #pragma unroll
            for (int ma = 0; ma < 2; ++ma) {
                mma_tf32(accg + (ma*4 + p*2 + 0)*4, a[ma], b[0], b[2]);
                mma_tf32(accg + (ma*4 + p*2 + 1)*4, a[ma], b[1], b[3]);
            }
            ldm_x4(sBm + off, b);
            #pragma unroll
            for (int ma = 0; ma < 2; ++ma) {
                mma_tf32(accm + (ma*4 + p*2 + 0)*4, a[ma], b[0], b[2]);
                mma_tf32(accm + (ma*4 + p*2 + 1)*4, a[ma], b[1], b[3]);
            }
        }
    }
}

// ---------------------------------------------------------------------------
// Stage 1: LN + 5 GEMMs. Dual-fused gate+main phases (8) + sg phases (4).
// 256 thr, 64-row tiles, 2 CTAs/SM.
// smem: Xf 64x132 f32 (33792) | ring 4x18432 (73728) = 107520 B
// Phase p (0..7): pass=p>>2, q=p&3; gate chunk (2*pass, q), main (2*pass+1, q).
// Pair slot p&1 -> bufs {0,1} or {2,3}. Prefetch: issue pair p+1 at phase p.
// ---------------------------------------------------------------------------
__device__ __forceinline__ void s1_load_pair(int p, uint32_t sRing, int tid) {
    int pass = p >> 2, q = p & 3, slot = (p & 1) * 2;
    loadWchunkTo(2 * pass,     q, slot,     sRing, tid);
    loadWchunkTo(2 * pass + 1, q, slot + 1, sRing, tid);
}

__global__ void __launch_bounds__(256, 2)
stage1_kernel(const float* __restrict__ x2d, const float* __restrict__ mask,
              const float* __restrict__ ga1, const float* __restrict__ be1,
              const float* __restrict__ bi,  const float* __restrict__ bis,
              const float* __restrict__ bj,  const float* __restrict__ bjs,
              const float* __restrict__ bs) {
    float* Xf = (float*)smem_;
    uint32_t sX = smem_u32(Xf);
    uint32_t sRing = sX + XFB;

    int tid = threadIdx.x, lane = tid & 31, w = tid >> 5;
    int wm = w >> 2, wn = w & 3;
    int g = lane >> 2, t2 = (lane & 3) * 2;
    size_t rowbase = (size_t)blockIdx.x * 64;

    s1_load_pair(0, sRing, tid);

    // layernorm: 4 threads/row, 32 channels each
    {
        int r = tid >> 2, e = tid & 3;
        const float* xr = x2d + (rowbase + r) * C + e * 32;
        float v[32], s = 0.f, ss = 0.f;
        #pragma unroll
        for (int t = 0; t < 8; ++t) {
            float4 f = *(const float4*)(xr + t * 4);
            v[4*t+0]=f.x; v[4*t+1]=f.y; v[4*t+2]=f.z; v[4*t+3]=f.w;
            s += f.x + f.y + f.z + f.w;
            ss += f.x*f.x + f.y*f.y + f.z*f.z + f.w*f.w;
        }
        s  += __shfl_xor_sync(0xffffffffu, s, 1);
        s  += __shfl_xor_sync(0xffffffffu, s, 2);
        ss += __shfl_xor_sync(0xffffffffu, ss, 1);
        ss += __shfl_xor_sync(0xffffffffu, ss, 2);
        float mu = s * (1.0f / C);
        float rs = rsqrtf(ss * (1.0f / C) - mu * mu + 1e-5f);
        #pragma unroll
        for (int t = 0; t < 32; ++t) {
            int k = e * 32 + t;
            Xf[r * 132 + k] = tf32r((v[t] - mu) * rs * __ldg(ga1 + k) + __ldg(be1 + k));
        }
    }

    float accg[32], accm[32];

    #pragma unroll 1
    for (int pass = 0; pass < 2; ++pass) {
        const float* bgp = pass ? bjs : bis;
        const float* bmp = pass ? bj  : bi;
        float* outp = pass ? g_j : g_i;

        #pragma unroll
        for (int q = 0; q < 32; ++q) { accg[q] = 0.f; accm[q] = 0.f; }

        #pragma unroll 1
        for (int q = 0; q < 4; ++q) {
            int p = pass * 4 + q;
            if (p + 1 < 8) { CP_WAIT(2); } else { CP_WAIT(0); }
            __syncthreads();
            if (p + 1 < 8) s1_load_pair(p + 1, sRing, tid);
            int slot = (p & 1) * 2;
            wgemm_chunk_dual(sX, (uint32_t)(q * 128),
                             sRing + (uint32_t)slot * WCH,
                             sRing + (uint32_t)(slot + 1) * WCH,
                             lane, wm, wn, accg, accm);
        }

        // epilogue: direct channel-major stores (sector-aligned scalar STG)
        #pragma unroll
        for (int ma = 0; ma < 2; ++ma) {
            int r0 = wm*32 + ma*16 + g;
            float m0 = __ldg(mask + rowbase + r0);
            float m1 = __ldg(mask + rowbase + r0 + 8);
            #pragma unroll
            for (int na = 0; na < 4; ++na) {
                int idx = (ma*4 + na) * 4;
                int c0 = wn*32 + na*8 + t2;
                float bg0 = __ldg(bgp + c0), bg1 = __ldg(bgp + c0 + 1);
                float b0 = __ldg(bmp + c0),  b1 = __ldg(bmp + c0 + 1);
                float* p0 = outp + (size_t)c0 * PLANE + rowbase + r0;
                float* p1 = outp + (size_t)(c0 + 1) * PLANE + rowbase + r0;
                p0[0] = tf32r((accm[idx+0] + b0) * sigmoidf_(accg[idx+0] + bg0) * m0);
                p1[0] = tf32r((accm[idx+1] + b1) * sigmoidf_(accg[idx+1] + bg1) * m0);
                p0[8] = tf32r((accm[idx+2] + b0) * sigmoidf_(accg[idx+2] + bg0) * m1);
                p1[8] = tf32r((accm[idx+3] + b1) * sigmoidf_(accg[idx+3] + bg1) * m1);
            }
        }
    }

    // sg = sigmoid(x@Ws+bs): 4 single chunks (m=4, q=0..3) into bufs 0..3
    __syncthreads();                        // all warps done with phase-7 bufs
    loadWchunkTo(4, 0, 0, sRing, tid);
    loadWchunkTo(4, 1, 1, sRing, tid);
    loadWchunkTo(4, 2, 2, sRing, tid);
    loadWchunkTo(4, 3, 3, sRing, tid);
    #pragma unroll
    for (int q = 0; q < 32; ++q) accg[q] = 0.f;
    #pragma unroll 1
    for (int q = 0; q < 4; ++q) {
        if      (q == 0) CP_WAIT(3);
        else if (q == 1) CP_WAIT(2);
        else if (q == 2) CP_WAIT(1);
        else             CP_WAIT(0);
        __syncthreads();
        wgemm_chunk(sX, (uint32_t)(q * 128), sRing + (uint32_t)q * WCH,
                    lane, wm, wn, accg);
    }
    #pragma unroll
    for (int ma = 0; ma < 2; ++ma) {
        size_t r0 = rowbase + wm*32 + ma*16 + g;
        #pragma unroll
        for (int na = 0; na < 4; ++na) {
            int idx = (ma*4 + na) * 4;
            int c0 = wn*32 + na*8 + t2;
            float b0 = __ldg(bs + c0), b1 = __ldg(bs + c0 + 1);
            *(float2*)(g_sg + r0 * C + c0) =
                make_float2(sigmoidf_(accg[idx+0] + b0), sigmoidf_(accg[idx+1] + b1));
            *(float2*)(g_sg + (r0 + 8) * C + c0) =
                make_float2(sigmoidf_(accg[idx+2] + b0), sigmoidf_(accg[idx+3] + b1));
        }
    }
}

// ---------------------------------------------------------------------------
// Stage 2: einsum, tf32, block 128x128, 256 threads, 2 CTAs/SM. (R13)
// 3-stage cp.async pipeline, ONE barrier per k-chunk.
// ---------------------------------------------------------------------------
#define ESTG 36864

__device__ __forceinline__ void e_load(uint32_t sdst,
                                       const char* pA, const char* pB,
                                       int kb, int tid) {
    #pragma unroll
    for (int it = 0; it < 4; ++it) {
        int idx = tid + it * 256;
        int row = idx >> 3, ch = idx & 7;
        cp16(sdst + row * 144 + ch * 16,
             pA + (size_t)row * 2048 + kb * 128 + ch * 16);
    }
    #pragma unroll
    for (int it = 0; it < 4; ++it) {
        int idx = tid + it * 256;
        int row = idx >> 3, ch = idx & 7;
        cp16(sdst + 18432 + row * 144 + ch * 16,
             pB + (size_t)row * 2048 + kb * 128 + ch * 16);
    }
}

__device__ __forceinline__ void e_mma(uint32_t st, int lane, int wm, int wn, float* acc) {
    int lr = lane & 7, sel = lane >> 3;
    uint32_t aRow = (uint32_t)((wm*32 + (sel & 1)*8 + lr) * 144 + (sel >> 1)*16);
    uint32_t bRow = (uint32_t)((wn*64 + (sel & 1)*8 + lr) * 144 + (sel >> 1)*16);
    uint32_t sA = st, sB = st + 18432;
    #pragma unroll
    for (int kk = 0; kk < 4; ++kk) {
        uint32_t a[2][4];
        #pragma unroll
        for (int ma = 0; ma < 2; ++ma)
            ldm_x4(sA + aRow + (uint32_t)(ma * 16 * 144 + kk * 32), a[ma]);
        #pragma unroll
        for (int p = 0; p < 4; ++p) {
            uint32_t b[4];
            ldm_x4(sB + bRow + (uint32_t)(p * 16 * 144 + kk * 32), b);
            #pragma unroll
            for (int ma = 0; ma < 2; ++ma) {
                mma_tf32(acc + (ma*8 + p*2 + 0)*4, a[ma], b[0], b[2]);
                mma_tf32(acc + (ma*8 + p*2 + 1)*4, a[ma], b[1], b[3]);
            }
        }
    }
}

__global__ void __launch_bounds__(256, 2)
einsum_kernel() {
    uint32_t sb = smem_u32(smem_);
    int tid = threadIdx.x, lane = tid & 31, w = tid >> 5;
    int wm = w >> 1, wn = w & 1;
    int g = lane >> 2, t2 = (lane & 3) * 2;
    int c = blockIdx.z;
    int ibase = blockIdx.x * 128, jbase = blockIdx.y * 128;

    const char* pA = (const char*)(g_i + (size_t)c * PLANE + (size_t)ibase * NDIM);
    const char* pB = (const char*)(g_j + (size_t)c * PLANE + (size_t)jbase * NDIM);

    float acc[64];
    #pragma unroll
    for (int q = 0; q < 64; ++q) acc[q] = 0.f;

    e_load(sb,        pA, pB, 0, tid); CP_COMMIT();
    e_load(sb + ESTG, pA, pB, 1, tid); CP_COMMIT();

    #pragma unroll 1
    for (int kb = 0; kb < 16; ++kb) {
        if (kb < 15) { CP_WAIT(1); } else { CP_WAIT(0); }
        __syncthreads();
        if (kb + 2 < 16) {
            e_load(sb + ((kb + 2) % 3) * ESTG, pA, pB, kb + 2, tid);
            CP_COMMIT();
        }
        e_mma(sb + (kb % 3) * ESTG, lane, wm, wn, acc);
    }

    float* O = g_ecm + (size_t)c * PLANE;
    #pragma unroll
    for (int ma = 0; ma < 2; ++ma) {
        size_t r0 = (size_t)(ibase + wm*32 + ma*16 + g);
        #pragma unroll
        for (int na = 0; na < 8; ++na) {
            int idx = (ma*8 + na) * 4;
            int c0 = jbase + wn*64 + na*8 + t2;
            *(float2*)(O + r0 * NDIM + c0)       = make_float2(acc[idx+0], acc[idx+1]);
            *(float2*)(O + (r0 + 8) * NDIM + c0) = make_float2(acc[idx+2], acc[idx+3]);
        }
    }
}

// ---------------------------------------------------------------------------
// Stage 3: 64-row tiles, 256 threads, 2 CTAs/SM. (R13)
// smem: XT 64x132 f32 (33792) | W (67584) = 101376 B
// ---------------------------------------------------------------------------
__global__ void __launch_bounds__(256, 2)
stage3_kernel(const float* __restrict__ mask,
              const float* __restrict__ ga2, const float* __restrict__ be2,
              const float* __restrict__ bp,  float* __restrict__ out) {
    float* XT = (float*)smem_;
    uint32_t sXT = smem_u32(XT);
    uint32_t sW  = sXT + XFB;

    int tid = threadIdx.x, lane = tid & 31, w = tid >> 5;
    int wm = w >> 2, wn = w & 3;
    int g = lane >> 2, t2 = (lane & 3) * 2;
    size_t rowbase = (size_t)blockIdx.x * 64;

    loadWf(5, sW, tid);
    CP_COMMIT();

    // gather channel-major einsum output + LN over channels
    {
        int r = tid >> 2, e = tid & 3;
        const float* base = g_ecm + (size_t)(e * 32) * PLANE + rowbase + r;
        float v[32], s = 0.f, ss = 0.f;
        #pragma unroll
        for (int t = 0; t < 32; ++t) {
            float x = __ldg(base + (size_t)t * PLANE);
            v[t] = x; s += x; ss += x * x;
        }
        s  += __shfl_xor_sync(0xffffffffu, s, 1);
        s  += __shfl_xor_sync(0xffffffffu, s, 2);
        ss += __shfl_xor_sync(0xffffffffu, ss, 1);
        ss += __shfl_xor_sync(0xffffffffu, ss, 2);
        float mu = s * (1.0f / C);
        float rs = rsqrtf(ss * (1.0f / C) - mu * mu + 1e-5f);
        #pragma unroll
        for (int t = 0; t < 32; ++t) {
            int k = e * 32 + t;
            XT[r * 132 + k] = tf32r((v[t] - mu) * rs * __ldg(ga2 + k) + __ldg(be2 + k));
        }
    }
    CP_WAIT(0);
    __syncthreads();

    float acc[32];
    #pragma unroll
    for (int q = 0; q < 32; ++q) acc[q] = 0.f;
    wgemm_t32(sXT, sW, lane, wm, wn, acc);

    #pragma unroll
    for (int ma = 0; ma < 2; ++ma) {
        size_t r0 = rowbase + wm*32 + ma*16 + g;
        float m0 = __ldg(mask + r0);
        float m1 = __ldg(mask + r0 + 8);
        #pragma unroll
        for (int na = 0; na < 4; ++na) {
            int idx = (ma*4 + na) * 4;
            int c0 = wn*32 + na*8 + t2;
            float b0 = __ldg(bp + c0), b1 = __ldg(bp + c0 + 1);
            float2 s0 = *(const float2*)(g_sg + r0 * C + c0);
            float2 s1 = *(const float2*)(g_sg + (r0 + 8) * C + c0);
            *(float2*)(out + r0 * C + c0) =
                make_float2((acc[idx+0] + b0) * s0.x * m0, (acc[idx+1] + b1) * s0.y * m0);
            *(float2*)(out + (r0 + 8) * C + c0) =
                make_float2((acc[idx+2] + b0) * s1.x * m1, (acc[idx+3] + b1) * s1.y * m1);
        }
    }
}

// ---------------------------------------------------------------------------
extern "C" void kernel_launch(void* const* d_in, const int* in_sizes, int n_in,
                              void* d_out, int out_size) {
    const float* x2d  = (const float*)d_in[0];
    const float* mask = (const float*)d_in[1];
    const float* ga1  = (const float*)d_in[2];
    const float* be1  = (const float*)d_in[3];
    const float* ga2  = (const float*)d_in[4];
    const float* be2  = (const float*)d_in[5];
    const float* Wi   = (const float*)d_in[6];
    const float* bi   = (const float*)d_in[7];
    const float* Wis  = (const float*)d_in[8];
    const float* bis  = (const float*)d_in[9];
    const float* Wj   = (const float*)d_in[10];
    const float* bj   = (const float*)d_in[11];
    const float* Wjs  = (const float*)d_in[12];
    const float* bjs  = (const float*)d_in[13];
    const float* Wp   = (const float*)d_in[14];
    const float* bp   = (const float*)d_in[15];
    const float* Ws   = (const float*)d_in[16];
    const float* bs   = (const float*)d_in[17];

    const int smem_s1 = XFB + 4 * WCH;  // 107520
    const int smem_e  = 3 * ESTG;       // 110592
    const int smem_s3 = XFB + WFB;      // 101376
    cudaFuncSetAttribute(stage1_kernel, cudaFuncAttributeMaxDynamicSharedMemorySize, smem_s1);
    cudaFuncSetAttribute(einsum_kernel, cudaFuncAttributeMaxDynamicSharedMemorySize, smem_e);
    cudaFuncSetAttribute(stage3_kernel, cudaFuncAttributeMaxDynamicSharedMemorySize, smem_s3);

    convert_w_kernel<<<6, 256>>>(Wis, Wi, Wjs, Wj, Ws, Wp);

    stage1_kernel<<<NN / 64, 256, smem_s1>>>(x2d, mask, ga1, be1,
                                             bi, bis, bj, bjs, bs);

    dim3 grid2(NDIM / 128, NDIM / 128, C);
    einsum_kernel<<<grid2, 256, smem_e>>>();

    stage3_kernel<<<NN / 64, 256, smem_s3>>>(mask, ga2, be2, bp, (float*)d_out);
}